// round 13
// baseline (speedup 1.0000x reference)
#include <cuda_runtime.h>
#include <cuda_fp16.h>
#include <math.h>
#include <stdint.h>

// ---------------------------------------------------------------------------
// bs=16, c_in=c_out=512, w_dim=512, L=2048, k=3, UP=DOWN=2, 17-tap Kaiser LPF
// Conv: FP16 implicit GEMM, mma.sync + ldmatrix, cp.async double-buffered.
// Tile 64o x 128l, 2 CTAs/SM, 2048 tiles -> 6.92 waves (1.2% tail waste).
// Conv runs with the GPU to itself (R12 lesson: overlap poisons L2 reuse).
// ---------------------------------------------------------------------------

#define BS   16
#define CIN  512
#define COUT 512
#define LEN  2048
#define WDIM 512

// ---------------- device scratch -------------------------------------------
__device__ float  g_cond[BS * CIN];
__device__ float  g_w2[COUT * CIN];
__device__ float  g_invw[COUT];
__device__ float  g_scale[BS * COUT];      // d[b,o] * invw[o]
__device__ float  g_inv_s;
__device__ __half g_yh[BS * COUT * LEN];   // conv output fp16 (32 MB)
__device__ __half g_xt[BS * LEN * CIN];    // fp16 scaled x, transposed (32 MB)
__device__ __half g_wh[3 * COUT * CIN];    // fp16 conv_w, [kk][o][i]

struct Filt { float up[17]; float dn[17]; };

// ---------------- K1: cond[b,c] (warp per (c,b)) ---------------------------
__global__ void cond_kernel(const float* __restrict__ w,
                            const float* __restrict__ aw,
                            const float* __restrict__ ab) {
    int gw = blockIdx.x * 8 + (threadIdx.x >> 5);
    int lane = threadIdx.x & 31;
    int c = gw & (CIN - 1);
    int b = gw >> 9;
    float acc = 0.f;
#pragma unroll
    for (int t = 0; t < 16; t++)
        acc = fmaf(aw[c * WDIM + lane + 32 * t], w[b * WDIM + lane + 32 * t], acc);
#pragma unroll
    for (int s = 16; s; s >>= 1) acc += __shfl_xor_sync(0xffffffffu, acc, s);
    if (lane == 0) g_cond[b * CIN + c] = acc + ab[c];
}

// ---------------- K2: inv_s ------------------------------------------------
__global__ void reduce_cond_kernel() {
    __shared__ float sm[256];
    float s = 0.f;
    for (int i = threadIdx.x; i < BS * CIN; i += 256) {
        float v = g_cond[i];
        s = fmaf(v, v, s);
    }
    sm[threadIdx.x] = s;
    __syncthreads();
    for (int off = 128; off; off >>= 1) {
        if (threadIdx.x < off) sm[threadIdx.x] += sm[threadIdx.x + off];
        __syncthreads();
    }
    if (threadIdx.x == 0) g_inv_s = rsqrtf(sm[0] / (float)(BS * CIN));
}

// ---------------- K3: fused weight stats + fp16 split ----------------------
__global__ void __launch_bounds__(128)
wsplit_kernel(const float* __restrict__ cw) {
    int o = blockIdx.x;
    int tid  = threadIdx.x;
    int lane = tid & 31;
    int wrp  = tid >> 5;
    __shared__ float sm1[4];

    float sumw2 = 0.f;
#pragma unroll
    for (int j = 0; j < 4; j++) {
        int i = tid * 4 + j;
        const float* p = cw + (size_t)o * (CIN * 3) + i * 3;
        float a = p[0], bq = p[1], c = p[2];
        float s3 = a * a + bq * bq + c * c;
        g_w2[o * CIN + i] = s3;
        sumw2 += s3;
        g_wh[(0 * COUT + o) * CIN + i] = __float2half_rn(a);
        g_wh[(1 * COUT + o) * CIN + i] = __float2half_rn(bq);
        g_wh[(2 * COUT + o) * CIN + i] = __float2half_rn(c);
    }
#pragma unroll
    for (int s = 16; s; s >>= 1) sumw2 += __shfl_xor_sync(0xffffffffu, sumw2, s);
    if (lane == 0) sm1[wrp] = sumw2;
    __syncthreads();
    if (tid == 0)
        g_invw[o] = rsqrtf((sm1[0] + sm1[1] + sm1[2] + sm1[3]) / (float)(CIN * 3));
}

// ---------------- K4: demod scale ------------------------------------------
__global__ void __launch_bounds__(128)
demod_kernel() {
    int o = blockIdx.x;
    int tid  = threadIdx.x;
    int lane = tid & 31;
    int wrp  = tid >> 5;
    __shared__ float sm2[4 * 16];

    float w2[4];
#pragma unroll
    for (int j = 0; j < 4; j++) w2[j] = g_w2[o * CIN + tid * 4 + j];

    float acc[16];
#pragma unroll
    for (int b = 0; b < 16; b++) acc[b] = 0.f;
#pragma unroll
    for (int j = 0; j < 4; j++) {
        int i = tid * 4 + j;
#pragma unroll
        for (int b = 0; b < 16; b++) {
            float cv = g_cond[b * CIN + i];
            acc[b] = fmaf(w2[j], cv * cv, acc[b]);
        }
    }
#pragma unroll
    for (int b = 0; b < 16; b++) {
#pragma unroll
        for (int s = 16; s; s >>= 1)
            acc[b] += __shfl_xor_sync(0xffffffffu, acc[b], s);
    }
    if (lane == 0) {
#pragma unroll
        for (int b = 0; b < 16; b++) sm2[wrp * 16 + b] = acc[b];
    }
    __syncthreads();
    if (tid < 16) {
        float dot = sm2[tid] + sm2[16 + tid] + sm2[32 + tid] + sm2[48 + tid];
        float invw = g_invw[o];
        float inv_s = g_inv_s;
        float f = invw * invw * inv_s * inv_s;
        g_scale[tid * COUT + o] = rsqrtf(f * dot + 1e-8f) * invw;
    }
}

// ---------------- K5: transpose + style-scale x -> fp16 [b][l][ch] ---------
__global__ void __launch_bounds__(256)
transpose_x_kernel(const float* __restrict__ x,
                   const float* __restrict__ norm_ema) {
    __shared__ float tile[32][33];
    __shared__ float sc[32];
    int b  = blockIdx.z;
    int c0 = blockIdx.y * 32;
    int l0 = blockIdx.x * 32;
    int tx = threadIdx.x & 31;
    int ty = threadIdx.x >> 5;   // 0..7
    if (ty == 0)
        sc[tx] = g_cond[b * CIN + c0 + tx] * g_inv_s * rsqrtf(norm_ema[0]);
    __syncthreads();
#pragma unroll
    for (int cy = 0; cy < 4; cy++) {
        int ch = ty + 8 * cy;
        tile[ch][tx] = x[((size_t)(b * CIN + c0 + ch)) * LEN + l0 + tx] * sc[ch];
    }
    __syncthreads();
#pragma unroll
    for (int cy = 0; cy < 4; cy++) {
        int lr = ty + 8 * cy;
        g_xt[((size_t)(b * LEN + l0 + lr)) * CIN + c0 + tx] =
            __float2half_rn(tile[tx][lr]);
    }
}

// ---------------- K6: FP16 conv, cp.async 2-stage, 2 CTAs/SM ---------------
// Tile 64 o x 128 l; 256 threads = 8 warps (wm 0..1 x wn 0..3),
// warp tile 32 o x 32 l. 2048 tiles / 296 slots = 6.92 waves.
#define BO   64
#define BLT  128
#define CI   32
#define XPAD 40
#define XROWS (BLT + 2)              // 130
#define WROWS (3 * BO)               // 192
#define XBUF_B (XROWS * XPAD * 2)    // 10400
#define WBUF_B (WROWS * XPAD * 2)    // 15360
#define STAGE_B (XBUF_B + WBUF_B)    // 25760
#define CONV_SMEM (2 * STAGE_B)      // 51520

__device__ __forceinline__ uint32_t smem_u32(const void* p) {
    uint32_t a;
    asm("{ .reg .u64 t; cvta.to.shared.u64 t, %1; cvt.u32.u64 %0, t; }"
        : "=r"(a) : "l"(p));
    return a;
}
__device__ __forceinline__ void cp16(uint32_t dst, const void* src, uint32_t valid) {
    asm volatile("{\n\t.reg .pred p;\n\tsetp.eq.u32 p, %2, 0;\n\t"
                 "cp.async.ca.shared.global [%0], [%1], 16, p;\n\t}"
                 :: "r"(dst), "l"(src), "r"(valid) : "memory");
}
__device__ __forceinline__ void cp_commit() {
    asm volatile("cp.async.commit_group;" ::: "memory");
}
template <int N>
__device__ __forceinline__ void cp_wait() {
    asm volatile("cp.async.wait_group %0;" :: "n"(N) : "memory");
}
__device__ __forceinline__ void ldsm4(uint32_t* r, uint32_t addr) {
    asm volatile("ldmatrix.sync.aligned.m8n8.x4.shared.b16 {%0,%1,%2,%3}, [%4];"
        : "=r"(r[0]), "=r"(r[1]), "=r"(r[2]), "=r"(r[3]) : "r"(addr));
}
__device__ __forceinline__ void mma16816h(float* c, const uint32_t a[4],
                                          uint32_t b0, uint32_t b1) {
    asm volatile(
        "mma.sync.aligned.m16n8k16.row.col.f32.f16.f16.f32 "
        "{%0,%1,%2,%3}, {%4,%5,%6,%7}, {%8,%9}, {%0,%1,%2,%3};"
        : "+f"(c[0]), "+f"(c[1]), "+f"(c[2]), "+f"(c[3])
        : "r"(a[0]), "r"(a[1]), "r"(a[2]), "r"(a[3]), "r"(b0), "r"(b1));
}

__global__ void __launch_bounds__(256, 2)
conv_mma_kernel(const float* __restrict__ conv_b) {
    extern __shared__ char smem[];
    uint32_t sbase = smem_u32(smem);

    int tid  = threadIdx.x;
    int warp = tid >> 5;
    int lane = tid & 31;
    int grp  = lane >> 2;
    int tig  = lane & 3;
    int wm   = warp >> 2;   // 0..1
    int wn   = warp & 3;    // 0..3

    int l0 = blockIdx.x * BLT;
    int o0 = blockIdx.y * BO;
    int b  = blockIdx.z;

    float acc[2][4][4];
#pragma unroll
    for (int mt = 0; mt < 2; mt++)
#pragma unroll
        for (int nt = 0; nt < 4; nt++)
#pragma unroll
            for (int r = 0; r < 4; r++) acc[mt][nt][r] = 0.f;

    const __half* xrow = g_xt + (size_t)b * LEN * CIN;

    int a_row_l = lane & 15;
    int a_col_l = ((lane >> 4) & 1) << 3;
    int b_row_l = (((lane >> 4) & 1) << 3) + (lane & 7);
    int b_col_l = ((lane >> 3) & 1) << 3;

    auto stage = [&](int c, int s) {
        int i0 = c * CI;
        uint32_t xb = sbase + s * STAGE_B;
        uint32_t wb = xb + XBUF_B;
        for (int idx = tid; idx < XROWS * 4 + WROWS * 4; idx += 256) {
            if (idx < XROWS * 4) {
                int n = idx >> 2, q = idx & 3;
                int gl = l0 - 1 + n;
                cp16(xb + n * (XPAD * 2) + q * 16,
                     xrow + (size_t)gl * CIN + i0 + q * 8,
                     (uint32_t)(gl >= 0 && gl < LEN));
            } else {
                int r = (idx - XROWS * 4) >> 2, q = idx & 3;
                int kk = r >> 6, o = r & 63;
                cp16(wb + r * (XPAD * 2) + q * 16,
                     g_wh + ((size_t)(kk * COUT) + o0 + o) * CIN + i0 + q * 8,
                     1u);
            }
        }
        cp_commit();
    };

    auto compute = [&](int s) {
        uint32_t xsm_b = sbase + s * STAGE_B;
        uint32_t wsm_b = xsm_b + XBUF_B;
#pragma unroll
        for (int kk = 0; kk < 3; kk++) {
#pragma unroll
            for (int k16 = 0; k16 < 2; k16++) {
                uint32_t a[2][4];
#pragma unroll
                for (int mt = 0; mt < 2; mt++) {
                    int row = kk * BO + wm * 32 + mt * 16 + a_row_l;
                    int col = k16 * 16 + a_col_l;
                    ldsm4(a[mt], wsm_b + (uint32_t)(row * XPAD + col) * 2u);
                }
                uint32_t bb[2][4];
#pragma unroll
                for (int ntp = 0; ntp < 2; ntp++) {
                    int row = wn * 32 + ntp * 16 + b_row_l + kk;
                    int col = k16 * 16 + b_col_l;
                    ldsm4(bb[ntp], xsm_b + (uint32_t)(row * XPAD + col) * 2u);
                }
#pragma unroll
                for (int ntp = 0; ntp < 2; ntp++) {
#pragma unroll
                    for (int h = 0; h < 2; h++) {
                        mma16816h(acc[0][2 * ntp + h], a[0], bb[ntp][2 * h],
                                  bb[ntp][2 * h + 1]);
                        mma16816h(acc[1][2 * ntp + h], a[1], bb[ntp][2 * h],
                                  bb[ntp][2 * h + 1]);
                    }
                }
            }
        }
    };

    stage(0, 0);
    for (int c = 0; c < 16; c++) {
        if (c + 1 < 16) {
            stage(c + 1, (c + 1) & 1);
            cp_wait<1>();
        } else {
            cp_wait<0>();
        }
        __syncthreads();
        compute(c & 1);
        __syncthreads();
    }

#pragma unroll
    for (int mt = 0; mt < 2; mt++) {
        int oA = o0 + wm * 32 + mt * 16 + grp;
        int oB = oA + 8;
        float scA = g_scale[b * COUT + oA], bbA = conv_b[oA];
        float scB = g_scale[b * COUT + oB], bbB = conv_b[oB];
#pragma unroll
        for (int nt = 0; nt < 4; nt++) {
            int l = l0 + wn * 32 + nt * 8 + 2 * tig;
            __half2 vA = __floats2half2_rn(fmaf(acc[mt][nt][0], scA, bbA),
                                           fmaf(acc[mt][nt][1], scA, bbA));
            __half2 vB = __floats2half2_rn(fmaf(acc[mt][nt][2], scB, bbB),
                                           fmaf(acc[mt][nt][3], scB, bbB));
            *(__half2*)&g_yh[((size_t)(b * COUT + oA)) * LEN + l] = vA;
            *(__half2*)&g_yh[((size_t)(b * COUT + oB)) * LEN + l] = vB;
        }
    }
}

// ---------------- K7: resample, register-blocked ---------------------------
__global__ void __launch_bounds__(256)
resample_kernel(float* __restrict__ out, Filt F) {
    __shared__ float ysm[2064];
    __shared__ float ue[2064], uo[2064];
    int bc = blockIdx.x;
    int t  = threadIdx.x;
    const __half* yrow = g_yh + (size_t)bc * LEN;

    if (t < 8) {
        ysm[t] = 0.f; ysm[2056 + t] = 0.f;
        ue[t]  = 0.f; ue[2056 + t]  = 0.f;
        uo[t]  = 0.f; uo[2056 + t]  = 0.f;
    }
    {
        uint4 v = ((const uint4*)yrow)[t];
        __half2* hp = (__half2*)&v;
        float2 p0 = __half22float2(hp[0]);
        float2 p1 = __half22float2(hp[1]);
        float2 p2 = __half22float2(hp[2]);
        float2 p3 = __half22float2(hp[3]);
        *(float4*)&ysm[8 + 8 * t]     = make_float4(p0.x, p0.y, p1.x, p1.y);
        *(float4*)&ysm[8 + 8 * t + 4] = make_float4(p2.x, p2.y, p3.x, p3.y);
    }
    __syncthreads();

    const float s2 = 1.41421356237f;
    {
        float w[16];
        *(float4*)&w[0]  = *(const float4*)&ysm[8 * t + 4];
        *(float4*)&w[4]  = *(const float4*)&ysm[8 * t + 8];
        *(float4*)&w[8]  = *(const float4*)&ysm[8 * t + 12];
        *(float4*)&w[12] = *(const float4*)&ysm[8 * t + 16];
        float e[8], o8[8];
#pragma unroll
        for (int p = 0; p < 8; p++) {
            float ev = 0.f, ov = 0.f;
#pragma unroll
            for (int j = 0; j < 9; j++) ev = fmaf(F.up[2 * j], w[p + j], ev);
#pragma unroll
            for (int j = 0; j < 8; j++) ov = fmaf(F.up[2 * j + 1], w[p + 1 + j], ov);
            e[p]  = (ev > 0.f ? ev : 0.1f * ev) * s2;
            o8[p] = (ov > 0.f ? ov : 0.1f * ov) * s2;
        }
        *(float4*)&ue[8 + 8 * t]     = make_float4(e[0], e[1], e[2], e[3]);
        *(float4*)&ue[8 + 8 * t + 4] = make_float4(e[4], e[5], e[6], e[7]);
        *(float4*)&uo[8 + 8 * t]     = make_float4(o8[0], o8[1], o8[2], o8[3]);
        *(float4*)&uo[8 + 8 * t + 4] = make_float4(o8[4], o8[5], o8[6], o8[7]);
    }
    __syncthreads();

    {
        float we[16], wo[16];
        *(float4*)&we[0]  = *(const float4*)&ue[8 * t + 4];
        *(float4*)&we[4]  = *(const float4*)&ue[8 * t + 8];
        *(float4*)&we[8]  = *(const float4*)&ue[8 * t + 12];
        *(float4*)&we[12] = *(const float4*)&ue[8 * t + 16];
        *(float4*)&wo[0]  = *(const float4*)&uo[8 * t + 4];
        *(float4*)&wo[4]  = *(const float4*)&uo[8 * t + 8];
        *(float4*)&wo[8]  = *(const float4*)&uo[8 * t + 12];
        *(float4*)&wo[12] = *(const float4*)&uo[8 * t + 16];
        float z[8];
#pragma unroll
        for (int p = 0; p < 8; p++) {
            float zv = 0.f;
#pragma unroll
            for (int j = 0; j < 9; j++) zv = fmaf(F.dn[2 * j], we[p + j], zv);
#pragma unroll
            for (int j = 0; j < 8; j++) zv = fmaf(F.dn[2 * j + 1], wo[p + j], zv);
            z[p] = zv;
        }
        float* orow = out + (size_t)bc * LEN + 8 * t;
        *(float4*)&orow[0] = make_float4(z[0], z[1], z[2], z[3]);
        *(float4*)&orow[4] = make_float4(z[4], z[5], z[6], z[7]);
    }
}

// ---------------- host: Kaiser-sinc filter ---------------------------------
static double bessel_i0(double x) {
    double s = 1.0, term = 1.0;
    for (int k = 1; k < 64; k++) {
        double h = x / (2.0 * k);
        term *= h * h;
        s += term;
        if (term < 1e-18 * s) break;
    }
    return s;
}
static void make_filter(float* f) {
    const double PI = 3.14159265358979323846;
    double i0b = bessel_i0(2.5);
    for (int i = 0; i < 17; i++) {
        int n = i - 8;
        float fv;
        if (n == 0) fv = 0.5f;
        else fv = (float)sin(0.5 * PI * (double)n) / ((float)(PI * (double)n) + 1e-8f);
        double r = (double)n / 8.0;
        double win = bessel_i0(2.5 * sqrt(1.0 - r * r)) / i0b;
        f[i] = (float)win * fv;
    }
}

// ---------------- launcher: R11 forked setup DAG (conv/resample solo) ------
extern "C" void kernel_launch(void* const* d_in, const int* in_sizes, int n_in,
                              void* d_out, int out_size) {
    const float* x        = (const float*)d_in[0];
    const float* w        = (const float*)d_in[1];
    const float* affine_w = (const float*)d_in[2];
    const float* affine_b = (const float*)d_in[3];
    const float* conv_w   = (const float*)d_in[4];
    const float* conv_b   = (const float*)d_in[5];
    const float* norm_ema = (const float*)d_in[6];
    float* out = (float*)d_out;

    Filt F;
    make_filter(F.up);
    make_filter(F.dn);

    cudaFuncSetAttribute(conv_mma_kernel,
                         cudaFuncAttributeMaxDynamicSharedMemorySize, CONV_SMEM);

    cudaStream_t s2 = 0;
    cudaEvent_t eF = 0, eW = 0, eR = 0, eT = 0;
    bool forked =
        (cudaStreamCreateWithFlags(&s2, cudaStreamNonBlocking) == cudaSuccess) &&
        (cudaEventCreateWithFlags(&eF, cudaEventDisableTiming) == cudaSuccess) &&
        (cudaEventCreateWithFlags(&eW, cudaEventDisableTiming) == cudaSuccess) &&
        (cudaEventCreateWithFlags(&eR, cudaEventDisableTiming) == cudaSuccess) &&
        (cudaEventCreateWithFlags(&eT, cudaEventDisableTiming) == cudaSuccess);

    dim3 tgrid(LEN / 32, CIN / 32, BS);
    dim3 cgrid(LEN / BLT, COUT / BO, BS);   // 16 x 8 x 16 = 2048 CTAs

    if (forked) {
        cudaEventRecord(eF, 0);
        cudaStreamWaitEvent(s2, eF, 0);
        wsplit_kernel<<<COUT, 128, 0, s2>>>(conv_w);
        cudaEventRecord(eW, s2);

        cond_kernel<<<1024, 256>>>(w, affine_w, affine_b);
        reduce_cond_kernel<<<1, 256>>>();
        cudaEventRecord(eR, 0);

        cudaStreamWaitEvent(s2, eR, 0);
        transpose_x_kernel<<<tgrid, 256, 0, s2>>>(x, norm_ema);
        cudaEventRecord(eT, s2);

        cudaStreamWaitEvent(0, eW, 0);
        demod_kernel<<<COUT, 128>>>();

        cudaStreamWaitEvent(0, eT, 0);   // join before conv; conv runs alone
        conv_mma_kernel<<<cgrid, 256, CONV_SMEM>>>(conv_b);
        resample_kernel<<<BS * COUT, 256>>>(out, F);
    } else {
        wsplit_kernel<<<COUT, 128>>>(conv_w);
        cond_kernel<<<1024, 256>>>(w, affine_w, affine_b);
        reduce_cond_kernel<<<1, 256>>>();
        demod_kernel<<<COUT, 128>>>();
        transpose_x_kernel<<<tgrid, 256>>>(x, norm_ema);
        conv_mma_kernel<<<cgrid, 256, CONV_SMEM>>>(conv_b);
        resample_kernel<<<BS * COUT, 256>>>(out, F);
    }
    // streams/events intentionally not destroyed (capture-safe; no device mem)
}

// round 15
// speedup vs baseline: 1.2441x; 1.2441x over previous
#include <cuda_runtime.h>
#include <cuda_fp16.h>
#include <math.h>
#include <stdint.h>

// ---------------------------------------------------------------------------
// bs=16, c_in=c_out=512, w_dim=512, L=2048, k=3, UP=DOWN=2, 17-tap Kaiser LPF
// Conv: FP16 implicit GEMM (frozen R11 config: 64o x 256l, warp 32x64,
// cp.async 2-stage, 2 CTAs/SM). Transpose: vectorized, stride-132 + XOR
// swizzle (aligned STS.128, conflict-free both phases).
// ---------------------------------------------------------------------------

#define BS   16
#define CIN  512
#define COUT 512
#define LEN  2048
#define WDIM 512

// ---------------- device scratch -------------------------------------------
__device__ float  g_cond[BS * CIN];
__device__ float  g_w2[COUT * CIN];
__device__ float  g_invw[COUT];
__device__ float  g_scale[BS * COUT];      // d[b,o] * invw[o]
__device__ float  g_inv_s;
__device__ __half g_yh[BS * COUT * LEN];   // conv output fp16 (32 MB)
__device__ __half g_xt[BS * LEN * CIN];    // fp16 scaled x, transposed (32 MB)
__device__ __half g_wh[3 * COUT * CIN];    // fp16 conv_w, [kk][o][i]

struct Filt { float up[17]; float dn[17]; };

// ---------------- K1: cond[b,c] (warp per (c,b)) ---------------------------
__global__ void cond_kernel(const float* __restrict__ w,
                            const float* __restrict__ aw,
                            const float* __restrict__ ab) {
    int gw = blockIdx.x * 8 + (threadIdx.x >> 5);
    int lane = threadIdx.x & 31;
    int c = gw & (CIN - 1);
    int b = gw >> 9;
    float acc = 0.f;
#pragma unroll
    for (int t = 0; t < 16; t++)
        acc = fmaf(aw[c * WDIM + lane + 32 * t], w[b * WDIM + lane + 32 * t], acc);
#pragma unroll
    for (int s = 16; s; s >>= 1) acc += __shfl_xor_sync(0xffffffffu, acc, s);
    if (lane == 0) g_cond[b * CIN + c] = acc + ab[c];
}

// ---------------- K2: inv_s ------------------------------------------------
__global__ void reduce_cond_kernel() {
    __shared__ float sm[256];
    float s = 0.f;
    for (int i = threadIdx.x; i < BS * CIN; i += 256) {
        float v = g_cond[i];
        s = fmaf(v, v, s);
    }
    sm[threadIdx.x] = s;
    __syncthreads();
    for (int off = 128; off; off >>= 1) {
        if (threadIdx.x < off) sm[threadIdx.x] += sm[threadIdx.x + off];
        __syncthreads();
    }
    if (threadIdx.x == 0) g_inv_s = rsqrtf(sm[0] / (float)(BS * CIN));
}

// ---------------- K3: fused weight stats + fp16 split ----------------------
__global__ void __launch_bounds__(128)
wsplit_kernel(const float* __restrict__ cw) {
    int o = blockIdx.x;
    int tid  = threadIdx.x;
    int lane = tid & 31;
    int wrp  = tid >> 5;
    __shared__ float sm1[4];

    float sumw2 = 0.f;
#pragma unroll
    for (int j = 0; j < 4; j++) {
        int i = tid * 4 + j;
        const float* p = cw + (size_t)o * (CIN * 3) + i * 3;
        float a = p[0], bq = p[1], c = p[2];
        float s3 = a * a + bq * bq + c * c;
        g_w2[o * CIN + i] = s3;
        sumw2 += s3;
        g_wh[(0 * COUT + o) * CIN + i] = __float2half_rn(a);
        g_wh[(1 * COUT + o) * CIN + i] = __float2half_rn(bq);
        g_wh[(2 * COUT + o) * CIN + i] = __float2half_rn(c);
    }
#pragma unroll
    for (int s = 16; s; s >>= 1) sumw2 += __shfl_xor_sync(0xffffffffu, sumw2, s);
    if (lane == 0) sm1[wrp] = sumw2;
    __syncthreads();
    if (tid == 0)
        g_invw[o] = rsqrtf((sm1[0] + sm1[1] + sm1[2] + sm1[3]) / (float)(CIN * 3));
}

// ---------------- K4: demod scale ------------------------------------------
__global__ void __launch_bounds__(128)
demod_kernel() {
    int o = blockIdx.x;
    int tid  = threadIdx.x;
    int lane = tid & 31;
    int wrp  = tid >> 5;
    __shared__ float sm2[4 * 16];

    float w2[4];
#pragma unroll
    for (int j = 0; j < 4; j++) w2[j] = g_w2[o * CIN + tid * 4 + j];

    float acc[16];
#pragma unroll
    for (int b = 0; b < 16; b++) acc[b] = 0.f;
#pragma unroll
    for (int j = 0; j < 4; j++) {
        int i = tid * 4 + j;
#pragma unroll
        for (int b = 0; b < 16; b++) {
            float cv = g_cond[b * CIN + i];
            acc[b] = fmaf(w2[j], cv * cv, acc[b]);
        }
    }
#pragma unroll
    for (int b = 0; b < 16; b++) {
#pragma unroll
        for (int s = 16; s; s >>= 1)
            acc[b] += __shfl_xor_sync(0xffffffffu, acc[b], s);
    }
    if (lane == 0) {
#pragma unroll
        for (int b = 0; b < 16; b++) sm2[wrp * 16 + b] = acc[b];
    }
    __syncthreads();
    if (tid < 16) {
        float dot = sm2[tid] + sm2[16 + tid] + sm2[32 + tid] + sm2[48 + tid];
        float invw = g_invw[o];
        float inv_s = g_inv_s;
        float f = invw * invw * inv_s * inv_s;
        g_scale[tid * COUT + o] = rsqrtf(f * dot + 1e-8f) * invw;
    }
}

// ---------------- K5: transpose + style-scale x -> fp16 [b][l][ch] ---------
// Tile 32 ch x 128 l, 256 threads. smem stride 132 floats (row base 16B-
// aligned), column swizzle g = q4 ^ (2*(ch>>3)):
//   read phase  (warp=ch, lane=q4): g bijective in lane -> STS.128 clean.
//   write phase (thread=(l,quad), ch=8*quad+2j): bank = 8j(+4) +
//     4*((u^2q)&7) + (l&3); u bit0 x q bits1-2 -> all 32 banks distinct.
__global__ void __launch_bounds__(256)
transpose_x_kernel(const float* __restrict__ x,
                   const float* __restrict__ norm_ema) {
    __shared__ float tile[32 * 132];
    __shared__ float sc[32];
    int b  = blockIdx.z;
    int c0 = blockIdx.y * 32;
    int l0 = blockIdx.x * 128;
    int tid = threadIdx.x;

    if (tid < 32)
        sc[tid] = g_cond[b * CIN + c0 + tid] * g_inv_s * rsqrtf(norm_ema[0]);
    __syncthreads();

    // read: 1024 float4 (32 ch x 32 quad-cols), 4 per thread
#pragma unroll
    for (int k = 0; k < 4; k++) {
        int id = tid + k * 256;
        int ch = id >> 5;
        int q4 = id & 31;
        float4 v = *(const float4*)&x[((size_t)(b * CIN + c0 + ch)) * LEN
                                      + l0 + q4 * 4];
        float s = sc[ch];
        v.x *= s; v.y *= s; v.z *= s; v.w *= s;
        int g = q4 ^ (2 * (ch >> 3));
        *(float4*)&tile[ch * 132 + g * 4] = v;
    }
    __syncthreads();

    // write: 512 uint4 (128 l x 4 ch-octets), 2 per thread
#pragma unroll
    for (int k = 0; k < 2; k++) {
        int id   = tid + k * 256;
        int l    = id >> 2;
        int quad = id & 3;
        int u = l >> 2, r = l & 3;
        int g = u ^ (2 * quad);          // ch>>3 == quad for all 8 ch here
        int colbase = g * 4 + r;
        uint32_t h[4];
#pragma unroll
        for (int j = 0; j < 4; j++) {
            float a = tile[(quad * 8 + 2 * j)     * 132 + colbase];
            float c = tile[(quad * 8 + 2 * j + 1) * 132 + colbase];
            __half2 p = __floats2half2_rn(a, c);
            h[j] = *(uint32_t*)&p;
        }
        *(uint4*)&g_xt[((size_t)(b * LEN + l0 + l)) * CIN + c0 + quad * 8] =
            make_uint4(h[0], h[1], h[2], h[3]);
    }
}

// ---------------- K6: FP16 conv (R11 frozen), cp.async 2-stage, 2 CTA/SM ---
#define BO   64
#define BLT  256
#define CI   32
#define XPAD 40
#define XROWS (BLT + 2)              // 258
#define WROWS (3 * BO)               // 192
#define XBUF_B (XROWS * XPAD * 2)    // 20640
#define WBUF_B (WROWS * XPAD * 2)    // 15360
#define STAGE_B (XBUF_B + WBUF_B)    // 36000
#define CONV_SMEM (2 * STAGE_B)      // 72000

__device__ __forceinline__ uint32_t smem_u32(const void* p) {
    uint32_t a;
    asm("{ .reg .u64 t; cvta.to.shared.u64 t, %1; cvt.u32.u64 %0, t; }"
        : "=r"(a) : "l"(p));
    return a;
}
__device__ __forceinline__ void cp16(uint32_t dst, const void* src, uint32_t valid) {
    asm volatile("{\n\t.reg .pred p;\n\tsetp.eq.u32 p, %2, 0;\n\t"
                 "cp.async.ca.shared.global [%0], [%1], 16, p;\n\t}"
                 :: "r"(dst), "l"(src), "r"(valid) : "memory");
}
__device__ __forceinline__ void cp_commit() {
    asm volatile("cp.async.commit_group;" ::: "memory");
}
template <int N>
__device__ __forceinline__ void cp_wait() {
    asm volatile("cp.async.wait_group %0;" :: "n"(N) : "memory");
}
__device__ __forceinline__ void ldsm4(uint32_t* r, uint32_t addr) {
    asm volatile("ldmatrix.sync.aligned.m8n8.x4.shared.b16 {%0,%1,%2,%3}, [%4];"
        : "=r"(r[0]), "=r"(r[1]), "=r"(r[2]), "=r"(r[3]) : "r"(addr));
}
__device__ __forceinline__ void mma16816h(float* c, const uint32_t a[4],
                                          uint32_t b0, uint32_t b1) {
    asm volatile(
        "mma.sync.aligned.m16n8k16.row.col.f32.f16.f16.f32 "
        "{%0,%1,%2,%3}, {%4,%5,%6,%7}, {%8,%9}, {%0,%1,%2,%3};"
        : "+f"(c[0]), "+f"(c[1]), "+f"(c[2]), "+f"(c[3])
        : "r"(a[0]), "r"(a[1]), "r"(a[2]), "r"(a[3]), "r"(b0), "r"(b1));
}

__global__ void __launch_bounds__(256, 2)
conv_mma_kernel(const float* __restrict__ conv_b) {
    extern __shared__ char smem[];
    uint32_t sbase = smem_u32(smem);

    int tid  = threadIdx.x;
    int warp = tid >> 5;
    int lane = tid & 31;
    int grp  = lane >> 2;
    int tig  = lane & 3;
    int wm   = warp >> 2;   // 0..1
    int wn   = warp & 3;    // 0..3

    int l0 = blockIdx.x * BLT;
    int o0 = blockIdx.y * BO;
    int b  = blockIdx.z;

    float acc[2][8][4];
#pragma unroll
    for (int mt = 0; mt < 2; mt++)
#pragma unroll
        for (int nt = 0; nt < 8; nt++)
#pragma unroll
            for (int r = 0; r < 4; r++) acc[mt][nt][r] = 0.f;

    const __half* xrow = g_xt + (size_t)b * LEN * CIN;

    int a_row_l = lane & 15;
    int a_col_l = ((lane >> 4) & 1) << 3;
    int b_row_l = (((lane >> 4) & 1) << 3) + (lane & 7);
    int b_col_l = ((lane >> 3) & 1) << 3;

    auto stage = [&](int c, int s) {
        int i0 = c * CI;
        uint32_t xb = sbase + s * STAGE_B;
        uint32_t wb = xb + XBUF_B;
        for (int idx = tid; idx < XROWS * 4 + WROWS * 4; idx += 256) {
            if (idx < XROWS * 4) {
                int n = idx >> 2, q = idx & 3;
                int gl = l0 - 1 + n;
                cp16(xb + n * (XPAD * 2) + q * 16,
                     xrow + (size_t)gl * CIN + i0 + q * 8,
                     (uint32_t)(gl >= 0 && gl < LEN));
            } else {
                int r = (idx - XROWS * 4) >> 2, q = idx & 3;
                int kk = r >> 6, o = r & 63;
                cp16(wb + r * (XPAD * 2) + q * 16,
                     g_wh + ((size_t)(kk * COUT) + o0 + o) * CIN + i0 + q * 8,
                     1u);
            }
        }
        cp_commit();
    };

    auto compute = [&](int s) {
        uint32_t xsm_b = sbase + s * STAGE_B;
        uint32_t wsm_b = xsm_b + XBUF_B;
#pragma unroll
        for (int kk = 0; kk < 3; kk++) {
#pragma unroll
            for (int k16 = 0; k16 < 2; k16++) {
                uint32_t a[2][4];
#pragma unroll
                for (int mt = 0; mt < 2; mt++) {
                    int row = kk * BO + wm * 32 + mt * 16 + a_row_l;
                    int col = k16 * 16 + a_col_l;
                    ldsm4(a[mt], wsm_b + (uint32_t)(row * XPAD + col) * 2u);
                }
                uint32_t bb[4][4];
#pragma unroll
                for (int ntp = 0; ntp < 4; ntp++) {
                    int row = wn * 64 + ntp * 16 + b_row_l + kk;
                    int col = k16 * 16 + b_col_l;
                    ldsm4(bb[ntp], xsm_b + (uint32_t)(row * XPAD + col) * 2u);
                }
#pragma unroll
                for (int ntp = 0; ntp < 4; ntp++) {
#pragma unroll
                    for (int h = 0; h < 2; h++) {
                        mma16816h(acc[0][2 * ntp + h], a[0], bb[ntp][2 * h],
                                  bb[ntp][2 * h + 1]);
                        mma16816h(acc[1][2 * ntp + h], a[1], bb[ntp][2 * h],
                                  bb[ntp][2 * h + 1]);
                    }
                }
            }
        }
    };

    stage(0, 0);
    for (int c = 0; c < 16; c++) {
        if (c + 1 < 16) {
            stage(c + 1, (c + 1) & 1);
            cp_wait<1>();
        } else {
            cp_wait<0>();
        }
        __syncthreads();
        compute(c & 1);
        __syncthreads();
    }

#pragma unroll
    for (int mt = 0; mt < 2; mt++) {
        int oA = o0 + wm * 32 + mt * 16 + grp;
        int oB = oA + 8;
        float scA = g_scale[b * COUT + oA], bbA = conv_b[oA];
        float scB = g_scale[b * COUT + oB], bbB = conv_b[oB];
#pragma unroll
        for (int nt = 0; nt < 8; nt++) {
            int l = l0 + wn * 64 + nt * 8 + 2 * tig;
            __half2 vA = __floats2half2_rn(fmaf(acc[mt][nt][0], scA, bbA),
                                           fmaf(acc[mt][nt][1], scA, bbA));
            __half2 vB = __floats2half2_rn(fmaf(acc[mt][nt][2], scB, bbB),
                                           fmaf(acc[mt][nt][3], scB, bbB));
            *(__half2*)&g_yh[((size_t)(b * COUT + oA)) * LEN + l] = vA;
            *(__half2*)&g_yh[((size_t)(b * COUT + oB)) * LEN + l] = vB;
        }
    }
}

// ---------------- K7: resample, register-blocked ---------------------------
__global__ void __launch_bounds__(256)
resample_kernel(float* __restrict__ out, Filt F) {
    __shared__ float ysm[2064];
    __shared__ float ue[2064], uo[2064];
    int bc = blockIdx.x;
    int t  = threadIdx.x;
    const __half* yrow = g_yh + (size_t)bc * LEN;

    if (t < 8) {
        ysm[t] = 0.f; ysm[2056 + t] = 0.f;
        ue[t]  = 0.f; ue[2056 + t]  = 0.f;
        uo[t]  = 0.f; uo[2056 + t]  = 0.f;
    }
    {
        uint4 v = ((const uint4*)yrow)[t];
        __half2* hp = (__half2*)&v;
        float2 p0 = __half22float2(hp[0]);
        float2 p1 = __half22float2(hp[1]);
        float2 p2 = __half22float2(hp[2]);
        float2 p3 = __half22float2(hp[3]);
        *(float4*)&ysm[8 + 8 * t]     = make_float4(p0.x, p0.y, p1.x, p1.y);
        *(float4*)&ysm[8 + 8 * t + 4] = make_float4(p2.x, p2.y, p3.x, p3.y);
    }
    __syncthreads();

    const float s2 = 1.41421356237f;
    {
        float w[16];
        *(float4*)&w[0]  = *(const float4*)&ysm[8 * t + 4];
        *(float4*)&w[4]  = *(const float4*)&ysm[8 * t + 8];
        *(float4*)&w[8]  = *(const float4*)&ysm[8 * t + 12];
        *(float4*)&w[12] = *(const float4*)&ysm[8 * t + 16];
        float e[8], o8[8];
#pragma unroll
        for (int p = 0; p < 8; p++) {
            float ev = 0.f, ov = 0.f;
#pragma unroll
            for (int j = 0; j < 9; j++) ev = fmaf(F.up[2 * j], w[p + j], ev);
#pragma unroll
            for (int j = 0; j < 8; j++) ov = fmaf(F.up[2 * j + 1], w[p + 1 + j], ov);
            e[p]  = (ev > 0.f ? ev : 0.1f * ev) * s2;
            o8[p] = (ov > 0.f ? ov : 0.1f * ov) * s2;
        }
        *(float4*)&ue[8 + 8 * t]     = make_float4(e[0], e[1], e[2], e[3]);
        *(float4*)&ue[8 + 8 * t + 4] = make_float4(e[4], e[5], e[6], e[7]);
        *(float4*)&uo[8 + 8 * t]     = make_float4(o8[0], o8[1], o8[2], o8[3]);
        *(float4*)&uo[8 + 8 * t + 4] = make_float4(o8[4], o8[5], o8[6], o8[7]);
    }
    __syncthreads();

    {
        float we[16], wo[16];
        *(float4*)&we[0]  = *(const float4*)&ue[8 * t + 4];
        *(float4*)&we[4]  = *(const float4*)&ue[8 * t + 8];
        *(float4*)&we[8]  = *(const float4*)&ue[8 * t + 12];
        *(float4*)&we[12] = *(const float4*)&ue[8 * t + 16];
        *(float4*)&wo[0]  = *(const float4*)&uo[8 * t + 4];
        *(float4*)&wo[4]  = *(const float4*)&uo[8 * t + 8];
        *(float4*)&wo[8]  = *(const float4*)&uo[8 * t + 12];
        *(float4*)&wo[12] = *(const float4*)&uo[8 * t + 16];
        float z[8];
#pragma unroll
        for (int p = 0; p < 8; p++) {
            float zv = 0.f;
#pragma unroll
            for (int j = 0; j < 9; j++) zv = fmaf(F.dn[2 * j], we[p + j], zv);
#pragma unroll
            for (int j = 0; j < 8; j++) zv = fmaf(F.dn[2 * j + 1], wo[p + j], zv);
            z[p] = zv;
        }
        float* orow = out + (size_t)bc * LEN + 8 * t;
        *(float4*)&orow[0] = make_float4(z[0], z[1], z[2], z[3]);
        *(float4*)&orow[4] = make_float4(z[4], z[5], z[6], z[7]);
    }
}

// ---------------- host: Kaiser-sinc filter ---------------------------------
static double bessel_i0(double x) {
    double s = 1.0, term = 1.0;
    for (int k = 1; k < 64; k++) {
        double h = x / (2.0 * k);
        term *= h * h;
        s += term;
        if (term < 1e-18 * s) break;
    }
    return s;
}
static void make_filter(float* f) {
    const double PI = 3.14159265358979323846;
    double i0b = bessel_i0(2.5);
    for (int i = 0; i < 17; i++) {
        int n = i - 8;
        float fv;
        if (n == 0) fv = 0.5f;
        else fv = (float)sin(0.5 * PI * (double)n) / ((float)(PI * (double)n) + 1e-8f);
        double r = (double)n / 8.0;
        double win = bessel_i0(2.5 * sqrt(1.0 - r * r)) / i0b;
        f[i] = (float)win * fv;
    }
}

// ---------------- launcher: forked setup DAG (conv/resample solo) ----------
extern "C" void kernel_launch(void* const* d_in, const int* in_sizes, int n_in,
                              void* d_out, int out_size) {
    const float* x        = (const float*)d_in[0];
    const float* w        = (const float*)d_in[1];
    const float* affine_w = (const float*)d_in[2];
    const float* affine_b = (const float*)d_in[3];
    const float* conv_w   = (const float*)d_in[4];
    const float* conv_b   = (const float*)d_in[5];
    const float* norm_ema = (const float*)d_in[6];
    float* out = (float*)d_out;

    Filt F;
    make_filter(F.up);
    make_filter(F.dn);

    cudaFuncSetAttribute(conv_mma_kernel,
                         cudaFuncAttributeMaxDynamicSharedMemorySize, CONV_SMEM);

    cudaStream_t s2 = 0;
    cudaEvent_t eF = 0, eW = 0, eR = 0, eT = 0;
    bool forked =
        (cudaStreamCreateWithFlags(&s2, cudaStreamNonBlocking) == cudaSuccess) &&
        (cudaEventCreateWithFlags(&eF, cudaEventDisableTiming) == cudaSuccess) &&
        (cudaEventCreateWithFlags(&eW, cudaEventDisableTiming) == cudaSuccess) &&
        (cudaEventCreateWithFlags(&eR, cudaEventDisableTiming) == cudaSuccess) &&
        (cudaEventCreateWithFlags(&eT, cudaEventDisableTiming) == cudaSuccess);

    dim3 tgrid(LEN / 128, CIN / 32, BS);    // 16 x 16 x 16 = 4096 CTAs
    dim3 cgrid(LEN / BLT, COUT / BO, BS);   // 8 x 8 x 16 = 1024 CTAs

    if (forked) {
        cudaEventRecord(eF, 0);
        cudaStreamWaitEvent(s2, eF, 0);
        wsplit_kernel<<<COUT, 128, 0, s2>>>(conv_w);
        cudaEventRecord(eW, s2);

        cond_kernel<<<1024, 256>>>(w, affine_w, affine_b);
        reduce_cond_kernel<<<1, 256>>>();
        cudaEventRecord(eR, 0);

        cudaStreamWaitEvent(s2, eR, 0);
        transpose_x_kernel<<<tgrid, 256, 0, s2>>>(x, norm_ema);
        cudaEventRecord(eT, s2);

        cudaStreamWaitEvent(0, eW, 0);
        demod_kernel<<<COUT, 128>>>();

        cudaStreamWaitEvent(0, eT, 0);   // join; conv runs alone
        conv_mma_kernel<<<cgrid, 256, CONV_SMEM>>>(conv_b);
        resample_kernel<<<BS * COUT, 256>>>(out, F);
    } else {
        wsplit_kernel<<<COUT, 128>>>(conv_w);
        cond_kernel<<<1024, 256>>>(w, affine_w, affine_b);
        reduce_cond_kernel<<<1, 256>>>();
        demod_kernel<<<COUT, 128>>>();
        transpose_x_kernel<<<tgrid, 256>>>(x, norm_ema);
        conv_mma_kernel<<<cgrid, 256, CONV_SMEM>>>(conv_b);
        resample_kernel<<<BS * COUT, 256>>>(out, F);
    }
    // streams/events intentionally not destroyed (capture-safe; no device mem)
}